// round 6
// baseline (speedup 1.0000x reference)
#include <cuda_runtime.h>
#include <cstdint>
#include <cstddef>

// ---------------- problem constants ----------------
static constexpr int E_EDGES = 131072;
static constexpr int T_TRIP  = 1048576;
static constexpr int H_DIM   = 256;
static constexpr int I_DIM   = 64;
static constexpr int NR      = 6;
static constexpr int NSR     = 42;
static constexpr int BAS     = 8;

// ---------------- scratch (static device memory) ----------------
__device__ float g_xr  [(size_t)E_EDGES * H_DIM];
__device__ float g_xji [(size_t)E_EDGES * H_DIM];
__device__ float g_bufA[(size_t)E_EDGES * H_DIM];
__device__ float g_bufB[(size_t)E_EDGES * H_DIM];
__device__ float g_xkjd[(size_t)E_EDGES * I_DIM];
__device__ float g_agg [(size_t)E_EDGES * I_DIM];
__device__ float g_s8  [(size_t)E_EDGES * BAS];
__device__ float g_wr  [622592];   // tf32-rounded weights, concatenated

// weight offsets inside g_wr
static constexpr int WO_JI   = 0;
static constexpr int WO_KJ   = 65536;
static constexpr int WO_B11  = 131072;
static constexpr int WO_B12  = 196608;
static constexpr int WO_LIN  = 262144;
static constexpr int WO_A11  = 327680;
static constexpr int WO_A12  = 393216;
static constexpr int WO_A21  = 458752;
static constexpr int WO_A22  = 524288;
static constexpr int WO_DOWN = 589824;   // 256*64
static constexpr int WO_UP   = 606208;   // 64*256

// ---------------- helpers ----------------
__device__ __forceinline__ uint32_t smem_to_u32(const void* p) {
    uint32_t a;
    asm("{ .reg .u64 t; cvta.to.shared.u64 t, %1; cvt.u32.u64 %0, t; }" : "=r"(a) : "l"(p));
    return a;
}
__device__ __forceinline__ uint32_t tf32r(float v) {
    uint32_t o; asm("cvt.rna.tf32.f32 %0, %1;" : "=r"(o) : "f"(v)); return o;
}
__device__ __forceinline__ float silu_f(float v) {
    return v * (1.0f / (1.0f + __expf(-v)));
}
__device__ __forceinline__ void cp_async16(uint32_t dst, const void* src) {
    asm volatile("cp.async.cg.shared.global [%0], [%1], 16;" :: "r"(dst), "l"(src));
}
__device__ __forceinline__ void mma_tf32(float d[4], const uint32_t a[4], const uint32_t b[2]) {
    asm volatile(
        "mma.sync.aligned.m16n8k8.row.col.f32.tf32.tf32.f32 "
        "{%0,%1,%2,%3}, {%4,%5,%6,%7}, {%8,%9}, {%0,%1,%2,%3};"
        : "+f"(d[0]), "+f"(d[1]), "+f"(d[2]), "+f"(d[3])
        : "r"(a[0]), "r"(a[1]), "r"(a[2]), "r"(a[3]), "r"(b[0]), "r"(b[1]));
}

// ============ plain mma.sync tf32 GEMM (proven): C = [res +] silu(A @ W [+ bias]) ============
template <int BN, int K>
__global__ void __launch_bounds__(256, 2)
mma_gemm(const float* __restrict__ A, const float* __restrict__ W,
         const float* __restrict__ bias, const float* __restrict__ res,
         float* __restrict__ C, int Nfull)
{
    constexpr int BM = 128, BK = 16, DEPTH = 3;
    constexpr int KT = K / BK;
    constexpr int AS_STRIDE = BK + 4;
    constexpr int AS_STAGE  = BM * AS_STRIDE;
    constexpr int BS_STRIDE = BN + 4;
    constexpr int BS_STAGE  = BK * BS_STRIDE;
    constexpr int NF = BN / 16;

    extern __shared__ float smf[];
    float* As = smf;
    float* Bs = smf + DEPTH * AS_STAGE;
    const uint32_t smemA = smem_to_u32(As);
    const uint32_t smemB = smem_to_u32(Bs);

    const int tid = threadIdx.x, lane = tid & 31, wid = tid >> 5;
    const int warpM = wid >> 1, warpN = wid & 1;
    const int row0 = blockIdx.x * BM;
    const int col0 = blockIdx.y * BN;
    const int g = lane >> 2, q = lane & 3;

    float acc[2][NF][4];
#pragma unroll
    for (int mf = 0; mf < 2; mf++)
#pragma unroll
        for (int nf = 0; nf < NF; nf++)
#pragma unroll
            for (int v = 0; v < 4; v++) acc[mf][nf][v] = 0.0f;

    auto load_stage = [&](int s, int kt) {
        const int k0 = kt * BK;
#pragma unroll
        for (int i = 0; i < 2; i++) {
            int id = tid + i * 256;
            int m = id >> 2, c4 = (id & 3) * 4;
            cp_async16(smemA + (uint32_t)(s * AS_STAGE + m * AS_STRIDE + c4) * 4,
                       A + (size_t)(row0 + m) * K + k0 + c4);
        }
        constexpr int BCH = BK * BN / 4;
#pragma unroll
        for (int i = 0; i < BCH / 256; i++) {
            int id = tid + i * 256;
            int k = id / (BN / 4), n4 = (id % (BN / 4)) * 4;
            cp_async16(smemB + (uint32_t)(s * BS_STAGE + k * BS_STRIDE + n4) * 4,
                       W + (size_t)(k0 + k) * Nfull + col0 + n4);
        }
    };

#pragma unroll
    for (int s = 0; s < DEPTH - 1; s++) {
        load_stage(s, s);
        asm volatile("cp.async.commit_group;" ::: "memory");
    }

    for (int it = 0; it < KT; it++) {
        asm volatile("cp.async.wait_group %0;" :: "n"(DEPTH - 2) : "memory");
        __syncthreads();
        const int nx = it + DEPTH - 1;
        if (nx < KT) load_stage(nx % DEPTH, nx);
        asm volatile("cp.async.commit_group;" ::: "memory");

        const int s = it % DEPTH;
        const float* Asb = As + s * AS_STAGE;
        const float* Bsb = Bs + s * BS_STAGE;
#pragma unroll
        for (int ks = 0; ks < 2; ks++) {
            uint32_t af[2][4];
            uint32_t bf[NF][2];
#pragma unroll
            for (int mf = 0; mf < 2; mf++) {
                int r = warpM * 32 + mf * 16 + g;
                af[mf][0] = __float_as_uint(Asb[r * AS_STRIDE + ks * 8 + q]);
                af[mf][1] = __float_as_uint(Asb[(r + 8) * AS_STRIDE + ks * 8 + q]);
                af[mf][2] = __float_as_uint(Asb[r * AS_STRIDE + ks * 8 + q + 4]);
                af[mf][3] = __float_as_uint(Asb[(r + 8) * AS_STRIDE + ks * 8 + q + 4]);
            }
#pragma unroll
            for (int nf = 0; nf < NF; nf++) {
                int c = warpN * (BN / 2) + nf * 8 + g;
                bf[nf][0] = __float_as_uint(Bsb[(ks * 8 + q) * BS_STRIDE + c]);
                bf[nf][1] = __float_as_uint(Bsb[(ks * 8 + q + 4) * BS_STRIDE + c]);
            }
#pragma unroll
            for (int mf = 0; mf < 2; mf++)
#pragma unroll
                for (int nf = 0; nf < NF; nf++)
                    mma_tf32(acc[mf][nf], af[mf], bf[nf]);
        }
    }

#pragma unroll
    for (int mf = 0; mf < 2; mf++) {
#pragma unroll
        for (int nf = 0; nf < NF; nf++) {
            const int col = col0 + warpN * (BN / 2) + nf * 8 + 2 * q;
            float bv0 = 0.0f, bv1 = 0.0f;
            if (bias) { bv0 = bias[col]; bv1 = bias[col + 1]; }
#pragma unroll
            for (int h = 0; h < 2; h++) {
                const int row = row0 + warpM * 32 + mf * 16 + g + h * 8;
                float v0 = acc[mf][nf][h * 2 + 0] + bv0;
                float v1 = acc[mf][nf][h * 2 + 1] + bv1;
                v0 = silu_f(v0);
                v1 = silu_f(v1);
                const size_t off = (size_t)row * Nfull + col;
                if (res) {
                    float2 r = *reinterpret_cast<const float2*>(res + off);
                    v0 += r.x; v1 += r.y;
                }
                uint2 o;
                o.x = tf32r(v0);
                o.y = tf32r(v1);
                *reinterpret_cast<uint2*>(C + off) = o;
            }
        }
    }
}

static constexpr int mma_smem(int BN) {
    return 3 * (128 * 20 + 16 * (BN + 4)) * 4;
}

// ============ fused double-GEMM kernel ============
// MODE 0: C = A + silu( silu(A@W1+b1) @ W2 + b2 )           (N1=N2=256)
// MODE 1: C = silu( (silu(A@W1+b1) * gate) @ W2 )           (N2=64, gate = s8 @ Wg)
// One CTA owns 128 rows; intermediate H kept in SMEM.
template <int MODE>
__global__ void __launch_bounds__(256, 1)
fused2_kernel(const float* __restrict__ A,
              const float* __restrict__ W1, const float* __restrict__ b1,
              const float* __restrict__ W2, const float* __restrict__ b2,
              const float* __restrict__ s8, const float* __restrict__ Wg,
              float* __restrict__ C, int round_out)
{
    constexpr int DEPTH = 3, BK = 16, KT = 16;    // K = 256
    constexpr int HS = 260;                        // H stride (4g+q conflict-free for A-frags)
    constexpr int WS = 276;                        // W slab stride (20q+g conflict-free for B-frags)
    constexpr int AS = 20;
    constexpr int N2  = (MODE == 0) ? 256 : 64;
    constexpr int NF2 = N2 / 32;                   // frags per warp, phase2

    extern __shared__ float sm[];
    float* H   = sm;                               // 128*260
    float* As  = H + 128 * HS;                     // DEPTH*128*20
    float* Ws  = As + DEPTH * 128 * AS;            // DEPTH*16*276
    float* B1s = Ws + DEPTH * 16 * WS;             // 256
    float* B2s = B1s + 256;                        // 256
    float* S8s = B2s + 256;                        // MODE1: 1024
    float* WGs = S8s + 1024;                       // MODE1: 2048

    const uint32_t uAs = smem_to_u32(As);
    const uint32_t uWs = smem_to_u32(Ws);

    const int tid = threadIdx.x, lane = tid & 31, wid = tid >> 5;
    const int warpM = wid >> 2, warpN = wid & 3;   // 2M x 4N, warp tile 64 x 64 (phase1)
    const int g = lane >> 2, q = lane & 3;
    const int row0 = blockIdx.x * 128;

    B1s[tid] = b1 ? b1[tid] : 0.0f;
    if (MODE == 0) B2s[tid] = b2 ? b2[tid] : 0.0f;
    if (MODE == 1) {
        reinterpret_cast<float4*>(S8s)[tid] =
            reinterpret_cast<const float4*>(s8 + (size_t)row0 * 8)[tid];
        reinterpret_cast<float4*>(WGs)[tid]       = reinterpret_cast<const float4*>(Wg)[tid];
        reinterpret_cast<float4*>(WGs)[tid + 256] = reinterpret_cast<const float4*>(Wg)[tid + 256];
    }

    auto loadA1 = [&](int s, int kt) {
#pragma unroll
        for (int i = 0; i < 2; i++) {
            int id = tid + i * 256;
            int m = id >> 2, c4 = (id & 3) * 4;
            cp_async16(uAs + (uint32_t)(s * 128 * AS + m * AS + c4) * 4,
                       A + (size_t)(row0 + m) * 256 + kt * BK + c4);
        }
    };
    auto loadW = [&](int s, int kt, const float* W, int ncols) {
        const int chunks = BK * ncols / 4;
        for (int id = tid; id < chunks; id += 256) {
            int k = id / (ncols / 4), n4 = (id % (ncols / 4)) * 4;
            cp_async16(uWs + (uint32_t)(s * 16 * WS + k * WS + n4) * 4,
                       W + (size_t)(kt * BK + k) * ncols + n4);
        }
    };

    float acc[4][8][4];

    // ----------------- phase 1: H = act(A @ W1 + b1) [* gate] -----------------
#pragma unroll
    for (int mf = 0; mf < 4; mf++)
#pragma unroll
        for (int nf = 0; nf < 8; nf++)
#pragma unroll
            for (int v = 0; v < 4; v++) acc[mf][nf][v] = 0.0f;

#pragma unroll
    for (int s = 0; s < DEPTH - 1; s++) {
        loadA1(s, s); loadW(s, s, W1, 256);
        asm volatile("cp.async.commit_group;" ::: "memory");
    }
    for (int it = 0; it < KT; it++) {
        asm volatile("cp.async.wait_group %0;" :: "n"(DEPTH - 2) : "memory");
        __syncthreads();
        const int nx = it + DEPTH - 1;
        if (nx < KT) { loadA1(nx % DEPTH, nx); loadW(nx % DEPTH, nx, W1, 256); }
        asm volatile("cp.async.commit_group;" ::: "memory");

        const int s = it % DEPTH;
        const float* Asb = As + s * 128 * AS;
        const float* Wsb = Ws + s * 16 * WS;
#pragma unroll
        for (int ks = 0; ks < 2; ks++) {
            uint32_t af[4][4];
#pragma unroll
            for (int mf = 0; mf < 4; mf++) {
                int r = warpM * 64 + mf * 16 + g;
                af[mf][0] = __float_as_uint(Asb[r * AS + ks * 8 + q]);
                af[mf][1] = __float_as_uint(Asb[(r + 8) * AS + ks * 8 + q]);
                af[mf][2] = __float_as_uint(Asb[r * AS + ks * 8 + q + 4]);
                af[mf][3] = __float_as_uint(Asb[(r + 8) * AS + ks * 8 + q + 4]);
            }
            uint32_t bf[8][2];
#pragma unroll
            for (int nf = 0; nf < 8; nf++) {
                int c = warpN * 64 + nf * 8 + g;
                bf[nf][0] = __float_as_uint(Wsb[(ks * 8 + q) * WS + c]);
                bf[nf][1] = __float_as_uint(Wsb[(ks * 8 + q + 4) * WS + c]);
            }
#pragma unroll
            for (int mf = 0; mf < 4; mf++)
#pragma unroll
                for (int nf = 0; nf < 8; nf++)
                    mma_tf32(acc[mf][nf], af[mf], bf[nf]);
        }
    }
    asm volatile("cp.async.wait_group 0;" ::: "memory");

    // epilogue 1 -> H (tf32-rounded)
#pragma unroll
    for (int mf = 0; mf < 4; mf++) {
#pragma unroll
        for (int nf = 0; nf < 8; nf++) {
            const int c = warpN * 64 + nf * 8 + 2 * q;
            const int r0 = warpM * 64 + mf * 16 + g, r1 = r0 + 8;
            float v00 = silu_f(acc[mf][nf][0] + B1s[c]);
            float v01 = silu_f(acc[mf][nf][1] + B1s[c + 1]);
            float v10 = silu_f(acc[mf][nf][2] + B1s[c]);
            float v11 = silu_f(acc[mf][nf][3] + B1s[c + 1]);
            if (MODE == 1) {
                float g00 = 0.f, g01 = 0.f, g10 = 0.f, g11 = 0.f;
#pragma unroll
                for (int j = 0; j < 8; j++) {
                    float w0 = WGs[j * 256 + c], w1 = WGs[j * 256 + c + 1];
                    g00 += S8s[r0 * 8 + j] * w0;  g01 += S8s[r0 * 8 + j] * w1;
                    g10 += S8s[r1 * 8 + j] * w0;  g11 += S8s[r1 * 8 + j] * w1;
                }
                v00 *= g00; v01 *= g01; v10 *= g10; v11 *= g11;
            }
            H[r0 * HS + c]     = __uint_as_float(tf32r(v00));
            H[r0 * HS + c + 1] = __uint_as_float(tf32r(v01));
            H[r1 * HS + c]     = __uint_as_float(tf32r(v10));
            H[r1 * HS + c + 1] = __uint_as_float(tf32r(v11));
        }
    }
    __syncthreads();

    // ----------------- phase 2: out = f(H @ W2 [+ b2]) [+ A] -----------------
#pragma unroll
    for (int mf = 0; mf < 4; mf++)
#pragma unroll
        for (int nf = 0; nf < NF2; nf++)
#pragma unroll
            for (int v = 0; v < 4; v++) acc[mf][nf][v] = 0.0f;

#pragma unroll
    for (int s = 0; s < DEPTH - 1; s++) {
        loadW(s, s, W2, N2);
        asm volatile("cp.async.commit_group;" ::: "memory");
    }
    for (int it = 0; it < KT; it++) {
        asm volatile("cp.async.wait_group %0;" :: "n"(DEPTH - 2) : "memory");
        __syncthreads();
        const int nx = it + DEPTH - 1;
        if (nx < KT) loadW(nx % DEPTH, nx, W2, N2);
        asm volatile("cp.async.commit_group;" ::: "memory");

        const int s = it % DEPTH;
        const float* Wsb = Ws + s * 16 * WS;
#pragma unroll
        for (int ks = 0; ks < 2; ks++) {
            const int k = it * BK + ks * 8 + q;
            uint32_t af[4][4];
#pragma unroll
            for (int mf = 0; mf < 4; mf++) {
                int r = warpM * 64 + mf * 16 + g;
                af[mf][0] = __float_as_uint(H[r * HS + k]);
                af[mf][1] = __float_as_uint(H[(r + 8) * HS + k]);
                af[mf][2] = __float_as_uint(H[r * HS + k + 4]);
                af[mf][3] = __float_as_uint(H[(r + 8) * HS + k + 4]);
            }
            uint32_t bf[NF2][2];
#pragma unroll
            for (int nf = 0; nf < NF2; nf++) {
                int c = warpN * (N2 / 4) + nf * 8 + g;
                bf[nf][0] = __float_as_uint(Wsb[(ks * 8 + q) * WS + c]);
                bf[nf][1] = __float_as_uint(Wsb[(ks * 8 + q + 4) * WS + c]);
            }
#pragma unroll
            for (int mf = 0; mf < 4; mf++)
#pragma unroll
                for (int nf = 0; nf < NF2; nf++)
                    mma_tf32(acc[mf][nf], af[mf], bf[nf]);
        }
    }
    asm volatile("cp.async.wait_group 0;" ::: "memory");

    // epilogue 2
#pragma unroll
    for (int mf = 0; mf < 4; mf++) {
#pragma unroll
        for (int nf = 0; nf < NF2; nf++) {
            const int c = warpN * (N2 / 4) + nf * 8 + 2 * q;
#pragma unroll
            for (int h = 0; h < 2; h++) {
                const int row = row0 + warpM * 64 + mf * 16 + g + h * 8;
                float v0 = acc[mf][nf][h * 2 + 0];
                float v1 = acc[mf][nf][h * 2 + 1];
                if (MODE == 0) {
                    v0 = silu_f(v0 + B2s[c]);
                    v1 = silu_f(v1 + B2s[c + 1]);
                    const size_t off = (size_t)row * 256 + c;
                    float2 r = *reinterpret_cast<const float2*>(A + off);
                    v0 += r.x; v1 += r.y;
                    uint2 o;
                    o.x = round_out ? tf32r(v0) : __float_as_uint(v0);
                    o.y = round_out ? tf32r(v1) : __float_as_uint(v1);
                    *reinterpret_cast<uint2*>(C + off) = o;
                } else {
                    v0 = silu_f(v0);
                    v1 = silu_f(v1);
                    const size_t off = (size_t)row * 64 + c;
                    uint2 o;
                    o.x = tf32r(v0);
                    o.y = tf32r(v1);
                    *reinterpret_cast<uint2*>(C + off) = o;
                }
            }
        }
    }
}

static constexpr int fused2_smem(int mode) {
    int base = (128 * 260 + 3 * 128 * 20 + 3 * 16 * 276 + 512) * 4;
    return mode == 1 ? base + (1024 + 2048) * 4 : base;
}

// ---------------- round x to tf32-representable fp32 ----------------
__global__ void round_copy_kernel(const float4* __restrict__ in, float4* __restrict__ out, int n4)
{
    int i = blockIdx.x * blockDim.x + threadIdx.x;
    int stride = gridDim.x * blockDim.x;
    for (; i < n4; i += stride) {
        float4 v = in[i];
        uint4 o;
        o.x = tf32r(v.x); o.y = tf32r(v.y); o.z = tf32r(v.z); o.w = tf32r(v.w);
        *reinterpret_cast<uint4*>(&out[i]) = o;
    }
}

// ---------------- round all weights, one launch ----------------
struct WSet { const float* src[11]; float* dst[11]; int n4[11]; };
__global__ void round_w_kernel(WSet ws)
{
    int seg = blockIdx.y;
    const float4* s = reinterpret_cast<const float4*>(ws.src[seg]);
    float4* d = reinterpret_cast<float4*>(ws.dst[seg]);
    int n4 = ws.n4[seg];
    for (int i = blockIdx.x * blockDim.x + threadIdx.x; i < n4; i += gridDim.x * blockDim.x) {
        float4 v = s[i];
        uint4 o;
        o.x = tf32r(v.x); o.y = tf32r(v.y); o.z = tf32r(v.z); o.w = tf32r(v.w);
        *reinterpret_cast<uint4*>(&d[i]) = o;
    }
}

// ---------------- s8 = rbf @ W_rbf1 : [E, 8] ----------------
__global__ void s8_kernel(const float* __restrict__ rbf, const float* __restrict__ W1,
                          float* __restrict__ s8out)
{
    __shared__ float w[NR * BAS];
    if (threadIdx.x < NR * BAS) w[threadIdx.x] = W1[threadIdx.x];
    __syncthreads();
    int e = blockIdx.x * blockDim.x + threadIdx.x;
    float r[NR];
#pragma unroll
    for (int i = 0; i < NR; i++) r[i] = __ldg(rbf + (size_t)e * NR + i);
    float o[BAS];
#pragma unroll
    for (int j = 0; j < BAS; j++) {
        float s = 0.f;
#pragma unroll
        for (int i = 0; i < NR; i++) s += r[i] * w[i * BAS + j];
        o[j] = s;
    }
    float4 o0 = make_float4(o[0], o[1], o[2], o[3]);
    float4 o1 = make_float4(o[4], o[5], o[6], o[7]);
    reinterpret_cast<float4*>(s8out)[e * 2 + 0] = o0;
    reinterpret_cast<float4*>(s8out)[e * 2 + 1] = o1;
}

// ---------------- zero scratch ----------------
__global__ void zero_kernel(float4* __restrict__ p, int n4)
{
    int i = blockIdx.x * blockDim.x + threadIdx.x;
    int stride = gridDim.x * blockDim.x;
    for (; i < n4; i += stride) p[i] = make_float4(0, 0, 0, 0);
}

// ---------------- triplet pass ----------------
__global__ void triplet_kernel(const float* __restrict__ sbf,
                               const int* __restrict__ idx_kj,
                               const int* __restrict__ idx_ji,
                               const float* __restrict__ W1,   // [42,8]
                               const float* __restrict__ W2,   // [8,64]
                               const float* __restrict__ xkjd, // [E,64]
                               float* __restrict__ agg)        // [E,64]
{
    __shared__ float sW1[NSR * BAS];
    __shared__ __align__(16) float sW2[BAS * I_DIM];
    for (int i = threadIdx.x; i < NSR * BAS; i += blockDim.x) sW1[i] = W1[i];
    for (int i = threadIdx.x; i < BAS * I_DIM; i += blockDim.x) sW2[i] = W2[i];
    __syncthreads();

    const int lane  = threadIdx.x & 31;
    const int wglob = (blockIdx.x * blockDim.x + threadIdx.x) >> 5;
    const int nwarp = (gridDim.x * blockDim.x) >> 5;
    const int sub = lane >> 4;
    const int sl  = lane & 15;
    const int j   = sl & 7;
    const int g   = sl >> 3;

    for (int p = wglob; p * 2 < T_TRIP; p += nwarp) {
        int t = p * 2 + sub;
        const float* srow = sbf + (size_t)t * NSR;
        float s = 0.f;
        for (int i = g; i < NSR; i += 2) s += srow[i] * sW1[i * BAS + j];
        s += __shfl_xor_sync(0xffffffffu, s, 8);

        int ekj = idx_kj[t];
        int eji = idx_ji[t];
        int c = sl * 4;
        float4 xv = *reinterpret_cast<const float4*>(&xkjd[(size_t)ekj * I_DIM + c]);
        float4 m = make_float4(0, 0, 0, 0);
#pragma unroll
        for (int jj = 0; jj < BAS; jj++) {
            float sj = __shfl_sync(0xffffffffu, s, (sub << 4) + jj);
            float4 w = *reinterpret_cast<const float4*>(&sW2[jj * I_DIM + c]);
            m.x += sj * w.x; m.y += sj * w.y; m.z += sj * w.z; m.w += sj * w.w;
        }
        m.x *= xv.x; m.y *= xv.y; m.z *= xv.z; m.w *= xv.w;
        atomicAdd(reinterpret_cast<float4*>(&agg[(size_t)eji * I_DIM + c]), m);
    }
}

// ---------------- launch ----------------
extern "C" void kernel_launch(void* const* d_in, const int* in_sizes, int n_in,
                              void* d_out, int out_size)
{
    const float* x      = (const float*)d_in[0];
    const float* rbf    = (const float*)d_in[1];
    const float* sbf    = (const float*)d_in[2];
    const int*   idx_kj = (const int*)d_in[3];
    const int*   idx_ji = (const int*)d_in[4];
    const float* W_ji   = (const float*)d_in[5];
    const float* b_ji   = (const float*)d_in[6];
    const float* W_kj   = (const float*)d_in[7];
    const float* b_kj   = (const float*)d_in[8];
    const float* W_rbf1 = (const float*)d_in[9];
    const float* W_rbf2 = (const float*)d_in[10];
    const float* W_sbf1 = (const float*)d_in[11];
    const float* W_sbf2 = (const float*)d_in[12];
    const float* W_down = (const float*)d_in[13];
    const float* W_up   = (const float*)d_in[14];
    const float* Wb1_1  = (const float*)d_in[15];
    const float* bb1_1  = (const float*)d_in[16];
    const float* Wb1_2  = (const float*)d_in[17];
    const float* bb1_2  = (const float*)d_in[18];
    const float* W_lin  = (const float*)d_in[19];
    const float* b_lin  = (const float*)d_in[20];
    const float* Wa1_1  = (const float*)d_in[21];
    const float* ba1_1  = (const float*)d_in[22];
    const float* Wa1_2  = (const float*)d_in[23];
    const float* ba1_2  = (const float*)d_in[24];
    const float* Wa2_1  = (const float*)d_in[25];
    const float* ba2_1  = (const float*)d_in[26];
    const float* Wa2_2  = (const float*)d_in[27];
    const float* ba2_2  = (const float*)d_in[28];
    float* out = (float*)d_out;

    float *xr, *xji, *bufA, *bufB, *xkjd, *agg, *s8b, *wr;
    cudaGetSymbolAddress((void**)&xr,   g_xr);
    cudaGetSymbolAddress((void**)&xji,  g_xji);
    cudaGetSymbolAddress((void**)&bufA, g_bufA);
    cudaGetSymbolAddress((void**)&bufB, g_bufB);
    cudaGetSymbolAddress((void**)&xkjd, g_xkjd);
    cudaGetSymbolAddress((void**)&agg,  g_agg);
    cudaGetSymbolAddress((void**)&s8b,  g_s8);
    cudaGetSymbolAddress((void**)&wr,   g_wr);

    constexpr int SM_BIG = mma_smem(128);
    constexpr int SM_F0  = fused2_smem(0);
    constexpr int SM_F1  = fused2_smem(1);
    cudaFuncSetAttribute(mma_gemm<128, 256>, cudaFuncAttributeMaxDynamicSharedMemorySize, SM_BIG);
    cudaFuncSetAttribute(mma_gemm<128, 64>,  cudaFuncAttributeMaxDynamicSharedMemorySize, SM_BIG);
    cudaFuncSetAttribute(fused2_kernel<0>,   cudaFuncAttributeMaxDynamicSharedMemorySize, SM_F0);
    cudaFuncSetAttribute(fused2_kernel<1>,   cudaFuncAttributeMaxDynamicSharedMemorySize, SM_F1);

    // 0: round x
    round_copy_kernel<<<1024, 256>>>((const float4*)x, (float4*)xr, E_EDGES * H_DIM / 4);

    // 1: round all weights (single launch)
    WSet ws;
    const float* srcs[11] = {W_ji, W_kj, Wb1_1, Wb1_2, W_lin, Wa1_1, Wa1_2, Wa2_1, Wa2_2, W_down, W_up};
    const int offs[11]    = {WO_JI, WO_KJ, WO_B11, WO_B12, WO_LIN, WO_A11, WO_A12, WO_A21, WO_A22, WO_DOWN, WO_UP};
    const int n4s[11]     = {16384, 16384, 16384, 16384, 16384, 16384, 16384, 16384, 16384, 4096, 4096};
    for (int i = 0; i < 11; i++) { ws.src[i] = srcs[i]; ws.dst[i] = wr + offs[i]; ws.n4[i] = n4s[i]; }
    round_w_kernel<<<dim3(16, 11), 256>>>(ws);

    // 2: zero agg
    zero_kernel<<<1024, 256>>>((float4*)agg, E_EDGES * I_DIM / 4);

    // 3: s8 = rbf @ W_rbf1
    s8_kernel<<<E_EDGES / 256, 256>>>(rbf, W_rbf1, s8b);

    // 4: x_ji = silu(x@W_ji + b)
    mma_gemm<128, 256><<<dim3(E_EDGES / 128, 2), 256, SM_BIG>>>(xr, wr + WO_JI, b_ji, nullptr, xji, H_DIM);

    // 5: fused kj -> gate -> down  => xkjd = silu((silu(x@W_kj+b) * (s8@W_rbf2)) @ W_down)
    fused2_kernel<1><<<E_EDGES / 128, 256, SM_F1>>>(
        xr, wr + WO_KJ, b_kj, wr + WO_DOWN, nullptr, s8b, W_rbf2, xkjd, 1);

    // 6: triplet message passing
    triplet_kernel<<<2048, 256>>>(sbf, idx_kj, idx_ji, W_sbf1, W_sbf2, xkjd, agg);

    // 7: h = x_ji + silu(agg @ W_up)
    mma_gemm<128, 64><<<dim3(E_EDGES / 128, 2), 256, SM_BIG>>>(agg, wr + WO_UP, nullptr, xji, bufA, H_DIM);

    // 8: fused pre-skip residual pair
    fused2_kernel<0><<<E_EDGES / 128, 256, SM_F0>>>(
        bufA, wr + WO_B11, bb1_1, wr + WO_B12, bb1_2, nullptr, nullptr, bufB, 1);

    // 9: skip: h = silu(h@W_lin+b) + x
    mma_gemm<128, 256><<<dim3(E_EDGES / 128, 2), 256, SM_BIG>>>(bufB, wr + WO_LIN, b_lin, x, bufA, H_DIM);

    // 10: fused post-skip residual pair 1
    fused2_kernel<0><<<E_EDGES / 128, 256, SM_F0>>>(
        bufA, wr + WO_A11, ba1_1, wr + WO_A12, ba1_2, nullptr, nullptr, bufB, 1);

    // 11: fused post-skip residual pair 2 -> final output (no rounding)
    fused2_kernel<0><<<E_EDGES / 128, 256, SM_F0>>>(
        bufB, wr + WO_A21, ba2_1, wr + WO_A22, ba2_2, nullptr, nullptr, out, 0);
}